// round 4
// baseline (speedup 1.0000x reference)
#include <cuda_runtime.h>
#include <cstdint>

#define N_NODES 50000
#define N_EDGES 800000
#define D 64
#define N_LAYERS 3

// Scratch (allocation-free rule: __device__ globals). float4 => 16B aligned.
__device__ float4 g_buf0[N_NODES * D / 4];
__device__ float4 g_buf1[N_NODES * D / 4];
__device__ float4 g_agg [N_NODES * D / 4];
__device__ int    g_cnt   [N_NODES];
__device__ int    g_rowptr[N_NODES + 1];
__device__ int    g_cursor[N_NODES];
__device__ int    g_col   [N_EDGES];

// ---------------------------------------------------------------------------
// CSR build step 1: zero per-node counters
// ---------------------------------------------------------------------------
__global__ void zero_cnt_kernel(int* __restrict__ cnt) {
    int i = blockIdx.x * blockDim.x + threadIdx.x;
    if (i < N_NODES) cnt[i] = 0;
}

// ---------------------------------------------------------------------------
// CSR build step 2: in-degree histogram
// ---------------------------------------------------------------------------
__global__ void hist_kernel(const int* __restrict__ dst, int* __restrict__ cnt) {
    int e = blockIdx.x * blockDim.x + threadIdx.x;
    if (e < N_EDGES) atomicAdd(&cnt[dst[e]], 1);
}

// ---------------------------------------------------------------------------
// CSR build step 3: exclusive prefix sum (single block, 1024 threads)
// Each thread scans a contiguous chunk; block-scan of per-thread totals.
// Writes row_ptr (exclusive) and cursor (= row_ptr copy for reorder).
// ---------------------------------------------------------------------------
#define SCAN_THREADS 1024
#define CHUNK ((N_NODES + SCAN_THREADS - 1) / SCAN_THREADS)   // 49

__global__ void __launch_bounds__(SCAN_THREADS) scan_kernel(
        const int* __restrict__ cnt,
        int* __restrict__ rowptr,
        int* __restrict__ cursor) {
    __shared__ int s[SCAN_THREADS];
    const int t = threadIdx.x;
    const int base = t * CHUNK;

    int total = 0;
    #pragma unroll 7
    for (int i = 0; i < CHUNK; i++) {
        int idx = base + i;
        if (idx < N_NODES) total += cnt[idx];
    }
    s[t] = total;
    __syncthreads();

    // Hillis-Steele inclusive scan -> convert to exclusive
    #pragma unroll
    for (int off = 1; off < SCAN_THREADS; off <<= 1) {
        int v = (t >= off) ? s[t - off] : 0;
        __syncthreads();
        s[t] += v;
        __syncthreads();
    }
    int run = (t == 0) ? 0 : s[t - 1];

    #pragma unroll 7
    for (int i = 0; i < CHUNK; i++) {
        int idx = base + i;
        if (idx < N_NODES) {
            rowptr[idx] = run;
            cursor[idx] = run;
            run += cnt[idx];
        }
    }
    if (t == 0) rowptr[N_NODES] = N_EDGES;
}

// ---------------------------------------------------------------------------
// CSR build step 4: reorder sources into per-destination buckets
// ---------------------------------------------------------------------------
__global__ void reorder_kernel(const int* __restrict__ src,
                               const int* __restrict__ dst,
                               int* __restrict__ cursor,
                               int* __restrict__ col) {
    int e = blockIdx.x * blockDim.x + threadIdx.x;
    if (e >= N_EDGES) return;
    int p = atomicAdd(&cursor[dst[e]], 1);
    col[p] = src[e];
}

// ---------------------------------------------------------------------------
// Aggregation: agg[n] = sum_{e in in(n)} x[col[e]]
// 16 lanes per node (one float4 each), 16 nodes per 256-thread block.
// Edge loop unrolled x4 for MLP against L2 latency. No atomics, no zeroing.
// ---------------------------------------------------------------------------
__global__ void __launch_bounds__(256) agg_kernel(
        const float4* __restrict__ x4,
        const int* __restrict__ rowptr,
        const int* __restrict__ col,
        float4* __restrict__ agg4) {
    const int n    = blockIdx.x * 16 + (threadIdx.x >> 4);
    const int lane = threadIdx.x & 15;
    const int beg = rowptr[n];
    const int end = rowptr[n + 1];

    float4 acc = make_float4(0.f, 0.f, 0.f, 0.f);
    int e = beg;
    for (; e + 4 <= end; e += 4) {
        int s0 = col[e], s1 = col[e + 1], s2 = col[e + 2], s3 = col[e + 3];
        float4 v0 = __ldg(x4 + (size_t)s0 * 16 + lane);
        float4 v1 = __ldg(x4 + (size_t)s1 * 16 + lane);
        float4 v2 = __ldg(x4 + (size_t)s2 * 16 + lane);
        float4 v3 = __ldg(x4 + (size_t)s3 * 16 + lane);
        acc.x += v0.x + v1.x + v2.x + v3.x;
        acc.y += v0.y + v1.y + v2.y + v3.y;
        acc.z += v0.z + v1.z + v2.z + v3.z;
        acc.w += v0.w + v1.w + v2.w + v3.w;
    }
    for (; e < end; e++) {
        float4 v = __ldg(x4 + (size_t)col[e] * 16 + lane);
        acc.x += v.x; acc.y += v.y; acc.z += v.z; acc.w += v.w;
    }
    agg4[(size_t)n * 16 + lane] = acc;
}

// ---------------------------------------------------------------------------
// Fused node update: out = relu?( x @ Wself + agg @ Wmsg + b )
// ---------------------------------------------------------------------------
#define SMEM_FLOATS (2 * 64 * 64 + 2 * 64 * 65)

__global__ void __launch_bounds__(256) node_gemm_kernel(
        const float* __restrict__ x,
        const float* __restrict__ agg,
        const float* __restrict__ Wself,
        const float* __restrict__ Wmsg,
        const float* __restrict__ bias,
        float* __restrict__ out,
        int apply_relu) {
    extern __shared__ float sm[];
    float* sWs = sm;                    // [64][64]
    float* sWm = sm + 64 * 64;          // [64][64]
    float* sX  = sm + 2 * 64 * 64;      // [64][65] padded
    float* sA  = sX + 64 * 65;          // [64][65] padded

    const int tid     = threadIdx.x;
    const int rowbase = blockIdx.x * 64;

    for (int i = tid; i < 64 * 64 / 4; i += 256) {
        reinterpret_cast<float4*>(sWs)[i] = reinterpret_cast<const float4*>(Wself)[i];
        reinterpret_cast<float4*>(sWm)[i] = reinterpret_cast<const float4*>(Wmsg)[i];
    }
    for (int i = tid; i < 64 * 16; i += 256) {
        int r = i >> 4;
        int c = i & 15;
        int grow = rowbase + r;
        float4 vx = make_float4(0.f, 0.f, 0.f, 0.f);
        float4 va = vx;
        if (grow < N_NODES) {
            vx = reinterpret_cast<const float4*>(x   + (size_t)grow * D)[c];
            va = reinterpret_cast<const float4*>(agg + (size_t)grow * D)[c];
        }
        float* dx = sX + r * 65 + c * 4;
        dx[0] = vx.x; dx[1] = vx.y; dx[2] = vx.z; dx[3] = vx.w;
        float* da = sA + r * 65 + c * 4;
        da[0] = va.x; da[1] = va.y; da[2] = va.z; da[3] = va.w;
    }
    __syncthreads();

    const int r  = tid >> 2;
    const int c0 = (tid & 3) * 16;

    float acc[16];
    #pragma unroll
    for (int j = 0; j < 16; j++) acc[j] = bias[c0 + j];

    #pragma unroll 8
    for (int k = 0; k < 64; k++) {
        float xv = sX[r * 65 + k];
        float av = sA[r * 65 + k];
        #pragma unroll
        for (int j = 0; j < 16; j += 4) {
            float4 ws = *reinterpret_cast<const float4*>(sWs + k * 64 + c0 + j);
            float4 wm = *reinterpret_cast<const float4*>(sWm + k * 64 + c0 + j);
            acc[j + 0] += xv * ws.x + av * wm.x;
            acc[j + 1] += xv * ws.y + av * wm.y;
            acc[j + 2] += xv * ws.z + av * wm.z;
            acc[j + 3] += xv * ws.w + av * wm.w;
        }
    }

    const int grow = rowbase + r;
    if (grow < N_NODES) {
        float* op = out + (size_t)grow * D + c0;
        #pragma unroll
        for (int j = 0; j < 16; j += 4) {
            float4 v;
            v.x = acc[j + 0]; v.y = acc[j + 1]; v.z = acc[j + 2]; v.w = acc[j + 3];
            if (apply_relu) {
                v.x = fmaxf(v.x, 0.f); v.y = fmaxf(v.y, 0.f);
                v.z = fmaxf(v.z, 0.f); v.w = fmaxf(v.w, 0.f);
            }
            *reinterpret_cast<float4*>(op + j) = v;
        }
    }
}

// ---------------------------------------------------------------------------
// Launch
// ---------------------------------------------------------------------------
extern "C" void kernel_launch(void* const* d_in, const int* in_sizes, int n_in,
                              void* d_out, int out_size) {
    (void)in_sizes; (void)n_in; (void)out_size;

    const float* x0    = (const float*)d_in[0];
    const int*   ei    = (const int*)d_in[1];      // int32 (JAX x64 disabled)
    const float* Wmsg  = (const float*)d_in[2];    // [3][64][64]
    const float* Wself = (const float*)d_in[3];    // [3][64][64]
    const float* bias  = (const float*)d_in[4];    // [3][64]
    float*       out   = (float*)d_out;

    const int* src = ei;
    const int* dst = ei + N_EDGES;

    float4 *buf0, *buf1, *agg;
    int *cnt, *rowptr, *cursor, *col;
    cudaGetSymbolAddress((void**)&buf0,   g_buf0);
    cudaGetSymbolAddress((void**)&buf1,   g_buf1);
    cudaGetSymbolAddress((void**)&agg,    g_agg);
    cudaGetSymbolAddress((void**)&cnt,    g_cnt);
    cudaGetSymbolAddress((void**)&rowptr, g_rowptr);
    cudaGetSymbolAddress((void**)&cursor, g_cursor);
    cudaGetSymbolAddress((void**)&col,    g_col);

    static bool attr_set = false;
    const int smem_bytes = SMEM_FLOATS * (int)sizeof(float);
    if (!attr_set) {
        cudaFuncSetAttribute(node_gemm_kernel,
                             cudaFuncAttributeMaxDynamicSharedMemorySize, smem_bytes);
        attr_set = true;
    }

    // ---- CSR build (graph is fixed within a call; rebuilt every call) ----
    zero_cnt_kernel<<<(N_NODES + 255) / 256, 256>>>(cnt);
    hist_kernel<<<(N_EDGES + 255) / 256, 256>>>(dst, cnt);
    scan_kernel<<<1, SCAN_THREADS>>>(cnt, rowptr, cursor);
    reorder_kernel<<<(N_EDGES + 255) / 256, 256>>>(src, dst, cursor, col);

    // ---- Layers ----
    const float* cur[N_LAYERS]  = { x0, (const float*)buf0, (const float*)buf1 };
    float*       next[N_LAYERS] = { (float*)buf0, (float*)buf1, out };

    const int agg_blocks  = N_NODES / 16;              // 3125
    const int gemm_blocks = (N_NODES + 63) / 64;       // 782

    for (int layer = 0; layer < N_LAYERS; layer++) {
        agg_kernel<<<agg_blocks, 256>>>(
            (const float4*)cur[layer], rowptr, col, agg);
        node_gemm_kernel<<<gemm_blocks, 256, smem_bytes>>>(
            cur[layer], (const float*)agg,
            Wself + (size_t)layer * D * D,
            Wmsg  + (size_t)layer * D * D,
            bias  + (size_t)layer * D,
            next[layer],
            layer < N_LAYERS - 1 ? 1 : 0);
    }
}